// round 5
// baseline (speedup 1.0000x reference)
#include <cuda_runtime.h>
#include <cuda_bf16.h>

// Problem constants
#define B_SZ 64
#define C_SZ 3
#define H_SZ 512
#define W_SZ 512
#define GRID 4
#define GH (H_SZ / GRID)        // 128 rows per grid-row slab
#define QTR 4                   // quarter-slabs per slab
#define QROWS (GH / QTR)        // 32 rows per block
#define NSLAB (B_SZ * GRID * C_SZ)   // 768
#define NBLK (NSLAB * QTR)           // 3072

// Scratch: per (slab, quarter, grid_col) partial sums.
// Every slot written exclusively by one block each launch -> no zeroing needed.
__device__ float g_q[NBLK * GRID];
__device__ unsigned int g_done = 0;   // reset by the last block each launch

// Each block (128 threads = 4 warps) reduces one quarter-slab: 32 rows x 512
// floats of one (b, grid_row, channel) unit. Per row (128 float4), lane i
// loads float4 positions i, i+32, i+64, i+96 -> grid columns 0..3, so each
// lane keeps 4 private accumulators. 3072 blocks of 4 warps -> ~21 blocks/SM
// of work at 16 resident -> ~1% wave-quantization loss (vs 15.6% at 768x256).
__global__ void __launch_bounds__(128) region_select_fused(
    const float* __restrict__ in, float* __restrict__ out) {
    const int blk  = blockIdx.x;          // [0, 3072)
    const int q    = blk & (QTR - 1);
    const int slab = blk >> 2;            // [0, 768) = (b*GRID+gr)*C_SZ + c
    const int c  = slab % C_SZ;
    const int gr = (slab / C_SZ) % GRID;
    const int b  = slab / (C_SZ * GRID);

    const size_t base_off =
        ((size_t)(b * C_SZ + c) * H_SZ + (size_t)gr * GH + (size_t)q * QROWS) * W_SZ;
    const float4* __restrict__ base = (const float4*)(in + base_off);
    // rows are 128 float4 wide

    const int warp = threadIdx.x >> 5;
    const int lane = threadIdx.x & 31;

    float a0 = 0.f, a1 = 0.f, a2 = 0.f, a3 = 0.f;

    #pragma unroll 4
    for (int r = warp; r < QROWS; r += 4) {
        const float4* __restrict__ row = base + (size_t)r * 128;
        float4 v0 = row[lane +  0];   // grid col 0
        float4 v1 = row[lane + 32];   // grid col 1
        float4 v2 = row[lane + 64];   // grid col 2
        float4 v3 = row[lane + 96];   // grid col 3
        a0 += (v0.x + v0.y) + (v0.z + v0.w);
        a1 += (v1.x + v1.y) + (v1.z + v1.w);
        a2 += (v2.x + v2.y) + (v2.z + v2.w);
        a3 += (v3.x + v3.y) + (v3.z + v3.w);
    }

    // Warp tree reduction (deterministic)
    #pragma unroll
    for (int off = 16; off > 0; off >>= 1) {
        a0 += __shfl_down_sync(0xFFFFFFFFu, a0, off);
        a1 += __shfl_down_sync(0xFFFFFFFFu, a1, off);
        a2 += __shfl_down_sync(0xFFFFFFFFu, a2, off);
        a3 += __shfl_down_sync(0xFFFFFFFFu, a3, off);
    }

    __shared__ float s[4][4];
    __shared__ bool s_last;
    if (lane == 0) {
        s[warp][0] = a0; s[warp][1] = a1; s[warp][2] = a2; s[warp][3] = a3;
    }
    __syncthreads();

    if (threadIdx.x < 4) {
        const int gc = threadIdx.x;
        float sum = (s[0][gc] + s[1][gc]) + (s[2][gc] + s[3][gc]);  // fixed order
        g_q[blk * GRID + gc] = sum;
    }

    // Publish this block's partials, then vote on being last.
    __threadfence();
    if (threadIdx.x == 0) {
        unsigned int old = atomicAdd(&g_done, 1u);
        s_last = (old == (unsigned)(NBLK - 1));
    }
    __syncthreads();
    if (!s_last) return;

    // ---- Last block: selection (threads 0..63, one per batch) ----
    if (threadIdx.x == 0) g_done = 0;   // reset for next graph replay
    __threadfence();

    const int bb = threadIdx.x;
    if (bb < B_SZ) {
        float cell[GRID][GRID];
        #pragma unroll
        for (int gr2 = 0; gr2 < GRID; ++gr2) {
            #pragma unroll
            for (int gc = 0; gc < GRID; ++gc) {
                float sum = 0.f;
                #pragma unroll
                for (int cc = 0; cc < C_SZ; ++cc) {
                    const int sl = (bb * GRID + gr2) * C_SZ + cc;
                    #pragma unroll
                    for (int qq = 0; qq < QTR; ++qq)
                        sum += g_q[(sl * QTR + qq) * GRID + gc];   // fixed order
                }
                cell[gr2][gc] = sum;
            }
        }

        float w[4];
        #pragma unroll
        for (int wr = 0; wr < 2; ++wr) {
            #pragma unroll
            for (int wc = 0; wc < 2; ++wc) {
                float sum = 0.f;
                #pragma unroll
                for (int i = 0; i < 3; ++i)
                    #pragma unroll
                    for (int j = 0; j < 3; ++j)
                        sum += cell[wr + i][wc + j];
                w[wr * 2 + wc] = sum;
            }
        }

        int best = 0;
        float bv = w[0];
        #pragma unroll
        for (int i = 1; i < 4; ++i) {
            if (w[i] > bv) { bv = w[i]; best = i; }   // strict > = first-index tie-break
        }

        out[bb * 2 + 0] = (float)(best >> 1);   // row
        out[bb * 2 + 1] = (float)(best & 1);    // col
    }
}

extern "C" void kernel_launch(void* const* d_in, const int* in_sizes, int n_in,
                              void* d_out, int out_size) {
    const float* sampling_map = (const float*)d_in[0];
    float* out = (float*)d_out;

    region_select_fused<<<NBLK, 128>>>(sampling_map, out);
}

// round 6
// speedup vs baseline: 1.4615x; 1.4615x over previous
#include <cuda_runtime.h>
#include <cuda_bf16.h>

// Problem constants
#define B_SZ 64
#define C_SZ 3
#define H_SZ 512
#define W_SZ 512
#define GRID 4
#define GH (H_SZ / GRID)             // 128 rows per slab
#define NBLK (B_SZ * GRID * C_SZ)    // 768

// Scratch: per (b, grid_row, channel, grid_col) partial sums.
// Every slot written exclusively by one block each launch -> no zeroing needed.
__device__ float g_part[B_SZ * GRID * C_SZ * GRID];
__device__ unsigned int g_done = 0;   // reset by the last block each launch

// Fused kernel, 768 blocks x 256 threads (all resident in one wave).
// Each block reduces one (b, grid_row, channel) slab = 128 rows x 512 floats.
// 8 warps/block, each warp sweeps 16 rows. Per row (128 float4), lane i loads
// float4 positions i, i+32, i+64, i+96 -> grid columns 0..3.
//
// KEY: #pragma unroll 1 keeps the consecutive-LDG batch at 4 per iteration
// (MLP_p1 ~ 4). The R5 experiment showed front-batching 16 LDG.128 at high
// occupancy triggers cross-CTA L1tex-queue contention (spread ~2.3x, DRAM 50%).
// Latency is hidden by ~41 resident warps/SM, not per-warp batch depth.
__global__ void __launch_bounds__(256) region_select_fused(
    const float* __restrict__ in, float* __restrict__ out) {
    const int blk = blockIdx.x;              // [0, 768)
    const int c  = blk % C_SZ;
    const int gr = (blk / C_SZ) % GRID;
    const int b  = blk / (C_SZ * GRID);

    const size_t base_off = ((size_t)(b * C_SZ + c) * H_SZ + (size_t)gr * GH) * W_SZ;
    const float4* __restrict__ base = (const float4*)(in + base_off);
    // rows are 128 float4 wide

    const int warp = threadIdx.x >> 5;
    const int lane = threadIdx.x & 31;

    float a0 = 0.f, a1 = 0.f, a2 = 0.f, a3 = 0.f;

    #pragma unroll 1
    for (int r = warp; r < GH; r += 8) {
        const float4* __restrict__ row = base + (size_t)r * 128;
        float4 v0 = row[lane +  0];   // grid col 0
        float4 v1 = row[lane + 32];   // grid col 1
        float4 v2 = row[lane + 64];   // grid col 2
        float4 v3 = row[lane + 96];   // grid col 3
        a0 += (v0.x + v0.y) + (v0.z + v0.w);
        a1 += (v1.x + v1.y) + (v1.z + v1.w);
        a2 += (v2.x + v2.y) + (v2.z + v2.w);
        a3 += (v3.x + v3.y) + (v3.z + v3.w);
    }

    // Warp tree reduction (deterministic)
    #pragma unroll
    for (int off = 16; off > 0; off >>= 1) {
        a0 += __shfl_down_sync(0xFFFFFFFFu, a0, off);
        a1 += __shfl_down_sync(0xFFFFFFFFu, a1, off);
        a2 += __shfl_down_sync(0xFFFFFFFFu, a2, off);
        a3 += __shfl_down_sync(0xFFFFFFFFu, a3, off);
    }

    __shared__ float s[8][4];
    __shared__ bool s_last;
    if (lane == 0) {
        s[warp][0] = a0; s[warp][1] = a1; s[warp][2] = a2; s[warp][3] = a3;
    }
    __syncthreads();

    if (threadIdx.x < 4) {
        const int gc = threadIdx.x;
        float sum = 0.f;
        #pragma unroll
        for (int w = 0; w < 8; ++w) sum += s[w][gc];   // fixed order -> deterministic
        g_part[((b * GRID + gr) * C_SZ + c) * GRID + gc] = sum;
    }

    // Publish this block's partials, then vote on being last.
    __threadfence();
    if (threadIdx.x == 0) {
        unsigned int old = atomicAdd(&g_done, 1u);
        s_last = (old == (unsigned)(NBLK - 1));
    }
    __syncthreads();
    if (!s_last) return;

    // ---- Last block: selection (threads 0..63, one per batch) ----
    if (threadIdx.x == 0) g_done = 0;   // reset for next graph replay
    __threadfence();

    const int bb = threadIdx.x;
    if (bb < B_SZ) {
        float cell[GRID][GRID];
        #pragma unroll
        for (int gr2 = 0; gr2 < GRID; ++gr2) {
            #pragma unroll
            for (int gc = 0; gc < GRID; ++gc) {
                float sum = 0.f;
                #pragma unroll
                for (int cc = 0; cc < C_SZ; ++cc)
                    sum += g_part[((bb * GRID + gr2) * C_SZ + cc) * GRID + gc];
                cell[gr2][gc] = sum;
            }
        }

        float w[4];
        #pragma unroll
        for (int wr = 0; wr < 2; ++wr) {
            #pragma unroll
            for (int wc = 0; wc < 2; ++wc) {
                float sum = 0.f;
                #pragma unroll
                for (int i = 0; i < 3; ++i)
                    #pragma unroll
                    for (int j = 0; j < 3; ++j)
                        sum += cell[wr + i][wc + j];
                w[wr * 2 + wc] = sum;
            }
        }

        int best = 0;
        float bv = w[0];
        #pragma unroll
        for (int i = 1; i < 4; ++i) {
            if (w[i] > bv) { bv = w[i]; best = i; }   // strict > = first-index tie-break
        }

        out[bb * 2 + 0] = (float)(best >> 1);   // row
        out[bb * 2 + 1] = (float)(best & 1);    // col
    }
}

extern "C" void kernel_launch(void* const* d_in, const int* in_sizes, int n_in,
                              void* d_out, int out_size) {
    const float* sampling_map = (const float*)d_in[0];
    float* out = (float*)d_out;

    region_select_fused<<<NBLK, 256>>>(sampling_map, out);
}